// round 8
// baseline (speedup 1.0000x reference)
#include <cuda_runtime.h>
#include <cstdint>

// ---------------- problem constants ----------------
#define Bb 8
#define Nn 131072          // F*T
#define Dd 40
#define P  48              // augmented row width (40 E + 4 V + 4 zero)
#define CELLS (P*P)        // 2304
#define CPB 54             // chunks per batch -> 432 CTAs @ 3/SM
#define CPBP 56            // padded chunk stride (floats), 16B aligned
#define CHUNK 2432         // 2 groups * 1216 rows
#define GROWS 1216         // rows per 4-warp group
#define TROWS 64           // rows per tile
#define GT 19              // tiles per group (1216/64)
#define ROWB 224           // staged row stride (56 floats) -> conflict-free frags
#define SSTAGE (TROWS*ROWB)          // 14336 B per stage
#define SMEM_BYTES (2*2*SSTAGE)      // 2 groups x 2 stages = 57344 B -> 3 CTAs/SM
#define FOLDW 13                     // fold stride (floats), conflict-free
#define K2_BLOCKS 72

// ---------------- device scratch ----------------
// layout: g_partials[(cell*Bb + b)*CPBP + chunk]
__device__ __align__(16) float g_partials[(size_t)CELLS * Bb * CPBP];
__device__ float g_blocksums[K2_BLOCKS];

// ---------------- PTX helpers ----------------
__device__ __forceinline__ uint32_t smem_u32(const void* p) {
    uint32_t a;
    asm("{ .reg .u64 t; cvta.to.shared.u64 t, %1; cvt.u32.u64 %0, t; }"
        : "=r"(a) : "l"(p));
    return a;
}

#define CVT_TF32(u, f) asm("cvt.rna.tf32.f32 %0, %1;" : "=r"(u) : "f"(f))
#define LDSF(v, a)     asm volatile("ld.shared.f32 %0, [%1];" : "=f"(v) : "r"(a))
#define CPASYNC(dst, src, sz) \
    asm volatile("cp.async.cg.shared.global [%0], [%1], 16, %2;" \
                 :: "r"(dst), "l"(src), "r"(sz) : "memory")
#define CPCOMMIT() asm volatile("cp.async.commit_group;" ::: "memory")
#define CPWAIT1()  asm volatile("cp.async.wait_group 1;" ::: "memory")
#define CPWAIT0()  asm volatile("cp.async.wait_group 0;" ::: "memory")
#define BARSYNC128(id) asm volatile("bar.sync %0, 128;" :: "r"(id) : "memory")

// D(16x8) += A(16x8,row) * B(8x8,col), tf32 inputs, f32 accum
#define MMA_TF32(dp, a0, a1, a2, a3, b0, b1) \
    asm volatile("mma.sync.aligned.m16n8k8.row.col.f32.tf32.tf32.f32 " \
        "{%0,%1,%2,%3}, {%4,%5,%6,%7}, {%8,%9}, {%0,%1,%2,%3};" \
        : "+f"((dp)[0]), "+f"((dp)[1]), "+f"((dp)[2]), "+f"((dp)[3]) \
        : "r"(a0), "r"(a1), "r"(a2), "r"(a3), "r"(b0), "r"(b1))

// ---- warp q stages its QUARTER of one 64-row tile ----
// E rows 16q..16q+15: lane handles row 16q+(lane>>1), half-row (lane&1): 5x16B.
// V rows: lanes 0..15 handle one 16B row each. Division-free addressing.
// Rows >= nrem zero-fill via src-size 0 (src clamped valid).
__device__ __forceinline__ void stage_q(uint32_t sbase,
                                        const char* __restrict__ Eb,
                                        const char* __restrict__ Vb,
                                        int nrem, int lane, int q)
{
    const int r    = 16 * q + (lane >> 1);
    const int half = (lane & 1) * 80;
    {
        const bool ok = (r < nrem);
        const uint32_t dst = sbase + (uint32_t)(r * ROWB + half);
        const char* src = ok ? (Eb + r * 160 + half) : Eb;
        const uint32_t sz = ok ? 16u : 0u;
        const int step = ok ? 16 : 0;
#pragma unroll
        for (int i = 0; i < 5; i++)
            CPASYNC(dst + i * 16, src + i * step, sz);
    }
    if (lane < 16) {
        const int rv = 16 * q + lane;
        const bool ok = (rv < nrem);
        const uint32_t dst = sbase + (uint32_t)(rv * ROWB + 160);
        const char* src = ok ? (Vb + rv * 16) : Vb;
        CPASYNC(dst, src, ok ? 16u : 0u);
    }
    CPCOMMIT();
}

// ============================================================
// Kernel 1: partial Gram G = X^T X per (batch, chunk), tf32 HMMA.
// 4-warp groups share a double-buffered 64-row slab; each warp stages
// a quarter and computes 3 of the 12 lower-triangle D tiles.
// ============================================================
__global__ __launch_bounds__(256, 3)
void gram_hmma_kernel(const float* __restrict__ E, const float* __restrict__ V)
{
    extern __shared__ float sm[];
    const int tid  = threadIdx.x;
    const int w    = tid >> 5;
    const int lane = tid & 31;
    const int g    = lane >> 2;   // 0..7
    const int tig  = lane & 3;    // 0..3
    const int gi   = w >> 2;      // group 0/1
    const int q    = w & 3;       // warp within group
    const int b     = blockIdx.y;
    const int chunk = blockIdx.x;

    // zero all smem once: feats 44..47 (+pad bytes) read as 0 forever
    {
        float4 z = make_float4(0.f, 0.f, 0.f, 0.f);
        for (int i = tid; i < SMEM_BYTES / 16; i += 256)
            ((float4*)sm)[i] = z;
    }
    __syncthreads();

    const int n_end  = min(Nn, (chunk + 1) * CHUNK);
    const int grp_n0 = chunk * CHUNK + gi * GROWS;
    const int nrem0  = n_end - grp_n0;
    const char* Eb = (const char*)(E + (size_t)b * Nn * Dd) + (size_t)grp_n0 * 160;
    const char* Vb = (const char*)(V + (size_t)b * Nn * 4) + (size_t)grp_n0 * 16;

    const uint32_t sgb = smem_u32(sm) + (uint32_t)(gi * 2 * SSTAGE);
    const int bar = gi + 1;

    // prologue: stage tiles 0 and 1
    stage_q(sgb,          Eb,              Vb,             nrem0,         lane, q);
    stage_q(sgb + SSTAGE, Eb + TROWS*160,  Vb + TROWS*16,  nrem0 - TROWS, lane, q);

    float d[12];
#pragma unroll
    for (int k = 0; k < 12; k++) d[k] = 0.f;

    for (int t = 0; t < GT; t++) {
        if (t + 1 < GT) CPWAIT1();
        else            CPWAIT0();
        BARSYNC128(bar);           // all 4 quarters landed + fenced

        const uint32_t cb = sgb + (uint32_t)((t & 1) * SSTAGE);

#pragma unroll
        for (int kk = 0; kk < 8; kk++) {
            const uint32_t ra = cb + (uint32_t)((kk * 8 + tig) * ROWB + g * 4);
            if (q == 0) {            // tiles (0,0)(0,1)(1,0): feats m=0..3
                float f0[4], f1[4]; uint32_t u0[4], u1[4];
#pragma unroll
                for (int m = 0; m < 4; m++) {
                    LDSF(f0[m], ra + m * 32);
                    LDSF(f1[m], ra + 4 * ROWB + m * 32);
                }
#pragma unroll
                for (int m = 0; m < 4; m++) { CVT_TF32(u0[m], f0[m]); CVT_TF32(u1[m], f1[m]); }
                MMA_TF32(&d[0], u0[0], u0[1], u1[0], u1[1], u0[0], u1[0]);
                MMA_TF32(&d[4], u0[0], u0[1], u1[0], u1[1], u0[1], u1[1]);
                MMA_TF32(&d[8], u0[2], u0[3], u1[2], u1[3], u0[0], u1[0]);
            } else if (q == 1) {     // tiles (1,1)(1,2)(1,3): feats m=1..3
                float f0[3], f1[3]; uint32_t u0[3], u1[3];
#pragma unroll
                for (int m = 0; m < 3; m++) {
                    LDSF(f0[m], ra + (m + 1) * 32);
                    LDSF(f1[m], ra + 4 * ROWB + (m + 1) * 32);
                }
#pragma unroll
                for (int m = 0; m < 3; m++) { CVT_TF32(u0[m], f0[m]); CVT_TF32(u1[m], f1[m]); }
                // A = feats 2,3 (=u[1],u[2]); B = feats 1,2,3 (=u[0],u[1],u[2])
                MMA_TF32(&d[0], u0[1], u0[2], u1[1], u1[2], u0[0], u1[0]);
                MMA_TF32(&d[4], u0[1], u0[2], u1[1], u1[2], u0[1], u1[1]);
                MMA_TF32(&d[8], u0[1], u0[2], u1[1], u1[2], u0[2], u1[2]);
            } else if (q == 2) {     // tiles (2,0)(2,1)(2,2): feats m=0,1,2,4,5
                float f0[5], f1[5]; uint32_t u0[5], u1[5];
                const int MM[5] = {0, 1, 2, 4, 5};
#pragma unroll
                for (int m = 0; m < 5; m++) {
                    LDSF(f0[m], ra + MM[m] * 32);
                    LDSF(f1[m], ra + 4 * ROWB + MM[m] * 32);
                }
#pragma unroll
                for (int m = 0; m < 5; m++) { CVT_TF32(u0[m], f0[m]); CVT_TF32(u1[m], f1[m]); }
                // A = feats 4,5 (=u[3],u[4]); B = feats 0,1,2
                MMA_TF32(&d[0], u0[3], u0[4], u1[3], u1[4], u0[0], u1[0]);
                MMA_TF32(&d[4], u0[3], u0[4], u1[3], u1[4], u0[1], u1[1]);
                MMA_TF32(&d[8], u0[3], u0[4], u1[3], u1[4], u0[2], u1[2]);
            } else {                 // tiles (2,3)(2,4)(2,5): feats m=3,4,5
                float f0[3], f1[3]; uint32_t u0[3], u1[3];
#pragma unroll
                for (int m = 0; m < 3; m++) {
                    LDSF(f0[m], ra + (m + 3) * 32);
                    LDSF(f1[m], ra + 4 * ROWB + (m + 3) * 32);
                }
#pragma unroll
                for (int m = 0; m < 3; m++) { CVT_TF32(u0[m], f0[m]); CVT_TF32(u1[m], f1[m]); }
                // A = feats 4,5 (=u[1],u[2]); B = feats 3,4,5 (=u[0],u[1],u[2])
                MMA_TF32(&d[0], u0[1], u0[2], u1[1], u1[2], u0[0], u1[0]);
                MMA_TF32(&d[4], u0[1], u0[2], u1[1], u1[2], u0[1], u1[1]);
                MMA_TF32(&d[8], u0[1], u0[2], u1[1], u1[2], u0[2], u1[2]);
            }
        }
        BARSYNC128(bar);           // all 4 warps done reading before overwrite

        if (t + 2 < GT)
            stage_q(cb, Eb + (size_t)(t + 2) * TROWS * 160,
                        Vb + (size_t)(t + 2) * TROWS * 16,
                        nrem0 - (t + 2) * TROWS, lane, q);
    }

    CPWAIT0();

    // ---- fold the CTA's 2 groups ----
    __syncthreads();
    {
        float* dst = sm + (size_t)(w * 32 + lane) * FOLDW;
#pragma unroll
        for (int k = 0; k < 12; k++) dst[k] = d[k];
    }
    __syncthreads();

    if (w < 4) {
        const float* f0 = sm + (size_t)(w * 32 + lane) * FOLDW;
        const float* f1 = sm + (size_t)((w + 4) * 32 + lane) * FOLDW;
#pragma unroll
        for (int k = 0; k < 12; k++) d[k] = f0[k] + f1[k];

        const int MT[4][3] = {{0,0,1},{1,1,1},{2,2,2},{2,2,2}};
        const int NT[4][3] = {{0,1,0},{1,2,3},{0,1,2},{3,4,5}};
#pragma unroll
        for (int f = 0; f < 3; f++) {
            const int i0 = 16 * MT[w][f] + g;
            const int j0 = 8 * NT[w][f] + 2 * tig;
#pragma unroll
            for (int h = 0; h < 2; h++) {    // rows i0, i0+8
                const int cell0 = (i0 + 8 * h) * P + j0;
                g_partials[(size_t)(cell0 * Bb + b) * CPBP + chunk]       = d[f*4 + 2*h];
                g_partials[(size_t)((cell0 + 1) * Bb + b) * CPBP + chunk] = d[f*4 + 2*h + 1];
            }
        }
    }
}

// ============================================================
// Kernel 2: per-(cell,batch) chunk reduction + weighted square.
// Contiguous 54-float rows (13x float4 + 2). Mirrors skipped tiles.
// ============================================================
__global__ __launch_bounds__(256)
void reduce1_kernel()
{
    const int idx = blockIdx.x * 256 + threadIdx.x;   // idx = cell*Bb + b
    float v = 0.f;
    if (idx < Bb * CELLS) {
        const int cell = idx >> 3;
        const int b    = idx & 7;
        const int i = cell / P;
        const int j = cell - i * P;
        const bool kept = (j >> 3) <= 2 * (i >> 4) + 1;   // tile was computed
        const int rcell = kept ? cell : (j * P + i);
        const float* pf = &g_partials[(size_t)(rcell * Bb + b) * CPBP];
        const float4* p4 = (const float4*)pf;
        float s = 0.f;
#pragma unroll
        for (int qq = 0; qq < 13; qq++) {
            float4 a = p4[qq];
            s += (a.x + a.y) + (a.z + a.w);
        }
        s += pf[52] + pf[53];
        const float wgt = ((i < Dd) == (j < Dd)) ? 1.0f : -1.0f;
        v = wgt * s * s;
    }
    __shared__ float red[256];
    red[threadIdx.x] = v;
    __syncthreads();
#pragma unroll
    for (int h = 128; h > 0; h >>= 1) {
        if (threadIdx.x < h) red[threadIdx.x] += red[threadIdx.x + h];
        __syncthreads();
    }
    if (threadIdx.x == 0) g_blocksums[blockIdx.x] = red[0];
}

// ============================================================
// Kernel 3: final scalar.
// ============================================================
__global__ __launch_bounds__(128)
void reduce2_kernel(float* __restrict__ out)
{
    __shared__ float s[128];
    const int t = threadIdx.x;
    s[t] = (t < K2_BLOCKS) ? g_blocksums[t] : 0.f;
    __syncthreads();
#pragma unroll
    for (int h = 64; h > 0; h >>= 1) {
        if (t < h) s[t] += s[t + h];
        __syncthreads();
    }
    if (t == 0) out[0] = s[0] / (float)((size_t)Bb * Nn);
}

// ============================================================
extern "C" void kernel_launch(void* const* d_in, const int* in_sizes, int n_in,
                              void* d_out, int out_size)
{
    const float* E = (const float*)d_in[0];
    const float* V = (const float*)d_in[1];
    if (n_in >= 2 && in_sizes[0] < in_sizes[1]) {
        const float* tmp = E; E = V; V = tmp;
    }

    cudaFuncSetAttribute(gram_hmma_kernel,
                         cudaFuncAttributeMaxDynamicSharedMemorySize, SMEM_BYTES);

    dim3 grid1(CPB, Bb);
    gram_hmma_kernel<<<grid1, 256, SMEM_BYTES>>>(E, V);
    reduce1_kernel<<<K2_BLOCKS, 256>>>();
    reduce2_kernel<<<1, 128>>>((float*)d_out);
}

// round 9
// speedup vs baseline: 1.6759x; 1.6759x over previous
#include <cuda_runtime.h>
#include <cstdint>

// ---------------- problem constants ----------------
#define Bb 8
#define Nn 131072          // F*T
#define Dd 40
#define P  48              // augmented row width (40 E + 4 V + 4 zero)
#define CELLS (P*P)        // 2304
#define CPB 54             // chunks per batch -> 432 CTAs @ 3/SM
#define CPBP 56            // padded chunk stride (floats), 16B aligned
#define CHUNK 2432         // 4 groups * 608 rows
#define GROWS 608          // rows per 2-warp group
#define TROWS 32           // rows per tile
#define GT 19              // tiles per group
#define ROWE 160           // E row stride (40 floats) -> conflict-free frags
#define SE_BYTES (TROWS*ROWE)        // 5120
#define SV_BYTES (TROWS*16)          // 512
#define SSTAGE (SE_BYTES+SV_BYTES)   // 5632 B per stage
#define STAGES 3
#define SMEM_BYTES (4*STAGES*SSTAGE) // 67584 B -> 3 CTAs/SM (202.8KB)
#define K2_BLOCKS 72

// ---------------- device scratch ----------------
// layout: g_partials[(cell*Bb + b)*CPBP + chunk]
__device__ __align__(16) float g_partials[(size_t)CELLS * Bb * CPBP];
__device__ float g_blocksums[K2_BLOCKS];

// ---------------- PTX helpers ----------------
__device__ __forceinline__ uint32_t smem_u32(const void* p) {
    uint32_t a;
    asm("{ .reg .u64 t; cvta.to.shared.u64 t, %1; cvt.u32.u64 %0, t; }"
        : "=r"(a) : "l"(p));
    return a;
}

#define CVT_TF32(u, f) asm("cvt.rna.tf32.f32 %0, %1;" : "=r"(u) : "f"(f))
#define LDSF(v, a)     asm volatile("ld.shared.f32 %0, [%1];" : "=f"(v) : "r"(a))
#define CPASYNC(dst, src, sz) \
    asm volatile("cp.async.cg.shared.global [%0], [%1], 16, %2;" \
                 :: "r"(dst), "l"(src), "r"(sz) : "memory")
#define CPCOMMIT() asm volatile("cp.async.commit_group;" ::: "memory")
#define CPWAIT2()  asm volatile("cp.async.wait_group 2;" ::: "memory")
#define CPWAIT1()  asm volatile("cp.async.wait_group 1;" ::: "memory")
#define CPWAIT0()  asm volatile("cp.async.wait_group 0;" ::: "memory")
#define BARSYNC64(id) asm volatile("bar.sync %0, 64;" :: "r"(id) : "memory")

// D(16x8) += A(16x8,row) * B(8x8,col), tf32 inputs, f32 accum
#define MMA_TF32(dp, a0, a1, a2, a3, b0, b1) \
    asm volatile("mma.sync.aligned.m16n8k8.row.col.f32.tf32.tf32.f32 " \
        "{%0,%1,%2,%3}, {%4,%5,%6,%7}, {%8,%9}, {%0,%1,%2,%3};" \
        : "+f"((dp)[0]), "+f"((dp)[1]), "+f"((dp)[2]), "+f"((dp)[3]) \
        : "r"(a0), "r"(a1), "r"(a2), "r"(a3), "r"(b0), "r"(b1))

// ---- warp p of a pair stages its half of one 32-row tile ----
// E: 320 contiguous 16B slots (rows contiguous in gmem AND smem, stride 160):
//    warp p takes 32-slot blocks 2i+p -> per-instruction contiguous 512B.
// V: 32 contiguous 16B slots, staged by warp p=1.
// Out-of-range slots zero-fill via src-size 0 (src clamped valid).
__device__ __forceinline__ void stage_half(uint32_t se, uint32_t sv,
                                           const char* __restrict__ Eb,
                                           const char* __restrict__ Vb,
                                           int nrem10, int nrem, int lane, int p)
{
#pragma unroll
    for (int i = 0; i < 5; i++) {
        const int q = i * 64 + p * 32 + lane;
        const bool ok = (q < nrem10);
        const char* src = ok ? (Eb + q * 16) : Eb;
        CPASYNC(se + (uint32_t)(q * 16), src, ok ? 16u : 0u);
    }
    if (p) {
        const bool ok = (lane < nrem);
        const char* src = ok ? (Vb + lane * 16) : Vb;
        CPASYNC(sv + (uint32_t)(lane * 16), src, ok ? 16u : 0u);
    }
    CPCOMMIT();
}

// ============================================================
// Kernel 1: partial Gram G = X^T X per (batch, chunk), tf32 HMMA.
// Warp pairs share a triple-buffered compact slab (E 160B rows + V 16B rows);
// each warp stages half the bytes, computes half the lower-triangle D tiles.
// ============================================================
__global__ __launch_bounds__(256, 3)
void gram_hmma_kernel(const float* __restrict__ E, const float* __restrict__ V)
{
    extern __shared__ float sm[];
    const int tid  = threadIdx.x;
    const int w    = tid >> 5;
    const int lane = tid & 31;
    const int g    = lane >> 2;   // 0..7
    const int tig  = lane & 3;    // 0..3
    const int gi   = w >> 1;      // warp-pair group 0..3
    const int p    = w & 1;       // parity within pair
    const int b     = blockIdx.y;
    const int chunk = blockIdx.x;

    const int n_end  = min(Nn, (chunk + 1) * CHUNK);
    const int grp_n0 = chunk * CHUNK + gi * GROWS;
    const int nrem0  = n_end - grp_n0;
    const char* Eb = (const char*)(E + (size_t)b * Nn * Dd) + (size_t)grp_n0 * 160;
    const char* Vb = (const char*)(V + (size_t)b * Nn * 4) + (size_t)grp_n0 * 16;

    const uint32_t sgb = smem_u32(sm) + (uint32_t)(gi * STAGES * SSTAGE);
    const int bar = gi + 1;

    // prologue: stage tiles 0,1,2 into buffers 0,1,2 (no zero-init needed:
    // every byte read later is cp.async-written, incl. zero-fill tails)
#pragma unroll
    for (int s = 0; s < 3; s++)
        stage_half(sgb + s * SSTAGE, sgb + s * SSTAGE + SE_BYTES,
                   Eb + (size_t)s * TROWS * 160, Vb + (size_t)s * TROWS * 16,
                   nrem0 * 10 - s * 320, nrem0 - s * TROWS, lane, p);

    float d[24];
#pragma unroll
    for (int k = 0; k < 24; k++) d[k] = 0.f;

    int buf = 0;
    for (int t = 0; t < GT; t++) {
        const int pend = GT - 1 - t;
        if (pend >= 2)      CPWAIT2();
        else if (pend == 1) CPWAIT1();
        else                CPWAIT0();
        BARSYNC64(bar);            // partner's half landed + fenced

        const uint32_t ce = sgb + (uint32_t)(buf * SSTAGE);
        const uint32_t cv = ce + SE_BYTES;

#pragma unroll
        for (int kk = 0; kk < 4; kk++) {
            const uint32_t ra = ce + (uint32_t)((kk * 8 + tig) * ROWE + g * 4);
            if (p == 0) {          // tiles (0,0)(0,1)(1,0)(1,1)(1,2)(1,3): feats m=0..3
                float f0[4], f1[4]; uint32_t u0[4], u1[4];
#pragma unroll
                for (int m = 0; m < 4; m++) {
                    LDSF(f0[m], ra + m * 32);
                    LDSF(f1[m], ra + 4 * ROWE + m * 32);
                }
#pragma unroll
                for (int m = 0; m < 4; m++) { CVT_TF32(u0[m], f0[m]); CVT_TF32(u1[m], f1[m]); }
                MMA_TF32(&d[0],  u0[0], u0[1], u1[0], u1[1], u0[0], u1[0]);
                MMA_TF32(&d[4],  u0[0], u0[1], u1[0], u1[1], u0[1], u1[1]);
                MMA_TF32(&d[8],  u0[2], u0[3], u1[2], u1[3], u0[0], u1[0]);
                MMA_TF32(&d[12], u0[2], u0[3], u1[2], u1[3], u0[1], u1[1]);
                MMA_TF32(&d[16], u0[2], u0[3], u1[2], u1[3], u0[2], u1[2]);
                MMA_TF32(&d[20], u0[2], u0[3], u1[2], u1[3], u0[3], u1[3]);
            } else {               // tiles (2,0..5): feats m=0..4 from E, m=5 from V(+zeros)
                float f0[5], f1[5]; uint32_t u0[6], u1[6];
#pragma unroll
                for (int m = 0; m < 5; m++) {
                    LDSF(f0[m], ra + m * 32);
                    LDSF(f1[m], ra + 4 * ROWE + m * 32);
                }
                float fv0 = 0.f, fv1 = 0.f;
                if (g < 4) {       // feats 40..43 live; 44..47 structurally zero
                    const uint32_t va = cv + (uint32_t)((kk * 8 + tig) * 16 + g * 4);
                    LDSF(fv0, va);
                    LDSF(fv1, va + 64);   // +4 rows * 16B
                }
#pragma unroll
                for (int m = 0; m < 5; m++) { CVT_TF32(u0[m], f0[m]); CVT_TF32(u1[m], f1[m]); }
                CVT_TF32(u0[5], fv0); CVT_TF32(u1[5], fv1);
                MMA_TF32(&d[0],  u0[4], u0[5], u1[4], u1[5], u0[0], u1[0]);
                MMA_TF32(&d[4],  u0[4], u0[5], u1[4], u1[5], u0[1], u1[1]);
                MMA_TF32(&d[8],  u0[4], u0[5], u1[4], u1[5], u0[2], u1[2]);
                MMA_TF32(&d[12], u0[4], u0[5], u1[4], u1[5], u0[3], u1[3]);
                MMA_TF32(&d[16], u0[4], u0[5], u1[4], u1[5], u0[4], u1[4]);
                MMA_TF32(&d[20], u0[4], u0[5], u1[4], u1[5], u0[5], u1[5]);
            }
        }
        BARSYNC64(bar);            // both warps done reading before overwrite

        if (t + 3 < GT)
            stage_half(ce, cv,
                       Eb + (size_t)(t + 3) * TROWS * 160,
                       Vb + (size_t)(t + 3) * TROWS * 16,
                       nrem0 * 10 - (t + 3) * 320, nrem0 - (t + 3) * TROWS, lane, p);

        buf = (buf == 2) ? 0 : buf + 1;
    }

    CPWAIT0();

    // ---- fold 4 groups: all warps dump accs, warps 0/1 sum their parity ----
    __syncthreads();
    {
        float* dst = sm + (size_t)(w * 32 + lane) * 25;   // odd stride
#pragma unroll
        for (int k = 0; k < 24; k++) dst[k] = d[k];
    }
    __syncthreads();

    if (w < 2) {
        const float* fold = sm;
#pragma unroll
        for (int k = 0; k < 24; k++) {
            float s = 0.f;
#pragma unroll
            for (int e = 0; e < 4; e++)
                s += fold[(size_t)(((w + 2 * e) * 32) + lane) * 25 + k];
            d[k] = s;
        }
        const int MT0[6] = {0,0,1,1,1,1};
        const int NT0[6] = {0,1,0,1,2,3};
#pragma unroll
        for (int f = 0; f < 6; f++) {
            const int i0 = (w == 0) ? (16 * MT0[f] + g) : (32 + g);
            const int j0 = ((w == 0) ? (8 * NT0[f]) : (8 * f)) + 2 * tig;
#pragma unroll
            for (int h = 0; h < 2; h++) {    // rows i0, i0+8
                const int cell0 = (i0 + 8 * h) * P + j0;
                g_partials[(size_t)(cell0 * Bb + b) * CPBP + chunk]       = d[f*4 + 2*h];
                g_partials[(size_t)((cell0 + 1) * Bb + b) * CPBP + chunk] = d[f*4 + 2*h + 1];
            }
        }
    }
}

// ============================================================
// Kernel 2: per-(cell,batch) chunk reduction + weighted square.
// Contiguous 54-float rows (13x float4 + 2). Mirrors skipped tiles.
// ============================================================
__global__ __launch_bounds__(256)
void reduce1_kernel()
{
    const int idx = blockIdx.x * 256 + threadIdx.x;   // idx = cell*Bb + b
    float v = 0.f;
    if (idx < Bb * CELLS) {
        const int cell = idx >> 3;
        const int b    = idx & 7;
        const int i = cell / P;
        const int j = cell - i * P;
        const bool kept = (j >> 3) <= 2 * (i >> 4) + 1;   // tile was computed
        const int rcell = kept ? cell : (j * P + i);
        const float* pf = &g_partials[(size_t)(rcell * Bb + b) * CPBP];
        const float4* p4 = (const float4*)pf;
        float s = 0.f;
#pragma unroll
        for (int qq = 0; qq < 13; qq++) {
            float4 a = p4[qq];
            s += (a.x + a.y) + (a.z + a.w);
        }
        s += pf[52] + pf[53];
        const float wgt = ((i < Dd) == (j < Dd)) ? 1.0f : -1.0f;
        v = wgt * s * s;
    }
    __shared__ float red[256];
    red[threadIdx.x] = v;
    __syncthreads();
#pragma unroll
    for (int h = 128; h > 0; h >>= 1) {
        if (threadIdx.x < h) red[threadIdx.x] += red[threadIdx.x + h];
        __syncthreads();
    }
    if (threadIdx.x == 0) g_blocksums[blockIdx.x] = red[0];
}

// ============================================================
// Kernel 3: final scalar.
// ============================================================
__global__ __launch_bounds__(128)
void reduce2_kernel(float* __restrict__ out)
{
    __shared__ float s[128];
    const int t = threadIdx.x;
    s[t] = (t < K2_BLOCKS) ? g_blocksums[t] : 0.f;
    __syncthreads();
#pragma unroll
    for (int h = 64; h > 0; h >>= 1) {
        if (t < h) s[t] += s[t + h];
        __syncthreads();
    }
    if (t == 0) out[0] = s[0] / (float)((size_t)Bb * Nn);
}

// ============================================================
extern "C" void kernel_launch(void* const* d_in, const int* in_sizes, int n_in,
                              void* d_out, int out_size)
{
    const float* E = (const float*)d_in[0];
    const float* V = (const float*)d_in[1];
    if (n_in >= 2 && in_sizes[0] < in_sizes[1]) {
        const float* tmp = E; E = V; V = tmp;
    }

    cudaFuncSetAttribute(gram_hmma_kernel,
                         cudaFuncAttributeMaxDynamicSharedMemorySize, SMEM_BYTES);

    dim3 grid1(CPB, Bb);
    gram_hmma_kernel<<<grid1, 256, SMEM_BYTES>>>(E, V);
    reduce1_kernel<<<K2_BLOCKS, 256>>>();
    reduce2_kernel<<<1, 128>>>((float*)d_out);
}

// round 10
// speedup vs baseline: 1.7372x; 1.0365x over previous
#include <cuda_runtime.h>
#include <cstdint>

// ---------------- problem constants ----------------
#define Bb 8
#define Nn 131072          // F*T
#define Dd 40
#define P  48              // augmented row width (40 E + 4 V + 4 zero)
#define CELLS (P*P)        // 2304
#define CPB 54             // chunks per batch -> 432 CTAs @ 3/SM
#define CHUNK 2432         // 4 groups * 608 rows
#define GROWS 608          // rows per 2-warp group
#define TROWS 32           // rows per tile
#define GT 19              // tiles per group
#define ROWE 160           // E row stride (40 floats) -> conflict-free frags
#define SE_BYTES (TROWS*ROWE)        // 5120
#define SV_BYTES (TROWS*16)          // 512
#define SSTAGE (SE_BYTES+SV_BYTES)   // 5632 B per stage
#define STAGES 3
#define SMEM_BYTES (4*STAGES*SSTAGE) // 67584 B -> 3 CTAs/SM
#define GOFF 6400                    // float offset of G block in smem (after fold area)
#define K2_BLOCKS 72

// ---------------- device scratch ----------------
// layout: g_partials[(b*CPB + chunk)*CELLS + cell]  -- contiguous per-CTA block
__device__ __align__(16) float g_partials[(size_t)Bb * CPB * CELLS];
__device__ float g_blocksums[K2_BLOCKS];

// ---------------- PTX helpers ----------------
__device__ __forceinline__ uint32_t smem_u32(const void* p) {
    uint32_t a;
    asm("{ .reg .u64 t; cvta.to.shared.u64 t, %1; cvt.u32.u64 %0, t; }"
        : "=r"(a) : "l"(p));
    return a;
}

#define CVT_TF32(u, f) asm("cvt.rna.tf32.f32 %0, %1;" : "=r"(u) : "f"(f))
#define LDSF(v, a)     asm volatile("ld.shared.f32 %0, [%1];" : "=f"(v) : "r"(a))
#define CPASYNC(dst, src, sz) \
    asm volatile("cp.async.cg.shared.global [%0], [%1], 16, %2;" \
                 :: "r"(dst), "l"(src), "r"(sz) : "memory")
#define CPCOMMIT() asm volatile("cp.async.commit_group;" ::: "memory")
#define CPWAIT2()  asm volatile("cp.async.wait_group 2;" ::: "memory")
#define CPWAIT1()  asm volatile("cp.async.wait_group 1;" ::: "memory")
#define CPWAIT0()  asm volatile("cp.async.wait_group 0;" ::: "memory")
#define BARSYNC64(id) asm volatile("bar.sync %0, 64;" :: "r"(id) : "memory")

// D(16x8) += A(16x8,row) * B(8x8,col), tf32 inputs, f32 accum
#define MMA_TF32(dp, a0, a1, a2, a3, b0, b1) \
    asm volatile("mma.sync.aligned.m16n8k8.row.col.f32.tf32.tf32.f32 " \
        "{%0,%1,%2,%3}, {%4,%5,%6,%7}, {%8,%9}, {%0,%1,%2,%3};" \
        : "+f"((dp)[0]), "+f"((dp)[1]), "+f"((dp)[2]), "+f"((dp)[3]) \
        : "r"(a0), "r"(a1), "r"(a2), "r"(a3), "r"(b0), "r"(b1))

// ---- warp p of a pair stages its half of one 32-row tile ----
__device__ __forceinline__ void stage_half(uint32_t se, uint32_t sv,
                                           const char* __restrict__ Eb,
                                           const char* __restrict__ Vb,
                                           int nrem10, int nrem, int lane, int p)
{
#pragma unroll
    for (int i = 0; i < 5; i++) {
        const int q = i * 64 + p * 32 + lane;
        const bool ok = (q < nrem10);
        const char* src = ok ? (Eb + q * 16) : Eb;
        CPASYNC(se + (uint32_t)(q * 16), src, ok ? 16u : 0u);
    }
    if (p) {
        const bool ok = (lane < nrem);
        const char* src = ok ? (Vb + lane * 16) : Vb;
        CPASYNC(sv + (uint32_t)(lane * 16), src, ok ? 16u : 0u);
    }
    CPCOMMIT();
}

// ============================================================
// Kernel 1: partial Gram G = X^T X per (batch, chunk), tf32 HMMA.
// Warp pairs, triple-buffered compact slab. Epilogue assembles the FULL
// symmetric G in smem and dumps one contiguous coalesced 9.2KB block.
// ============================================================
__global__ __launch_bounds__(256, 3)
void gram_hmma_kernel(const float* __restrict__ E, const float* __restrict__ V)
{
    extern __shared__ float sm[];
    const int tid  = threadIdx.x;
    const int w    = tid >> 5;
    const int lane = tid & 31;
    const int g    = lane >> 2;   // 0..7
    const int tig  = lane & 3;    // 0..3
    const int gi   = w >> 1;      // warp-pair group 0..3
    const int p    = w & 1;       // parity within pair
    const int b     = blockIdx.y;
    const int chunk = blockIdx.x;

    const int n_end  = min(Nn, (chunk + 1) * CHUNK);
    const int grp_n0 = chunk * CHUNK + gi * GROWS;
    const int nrem0  = n_end - grp_n0;
    const char* Eb = (const char*)(E + (size_t)b * Nn * Dd) + (size_t)grp_n0 * 160;
    const char* Vb = (const char*)(V + (size_t)b * Nn * 4) + (size_t)grp_n0 * 16;

    const uint32_t sgb = smem_u32(sm) + (uint32_t)(gi * STAGES * SSTAGE);
    const int bar = gi + 1;

    // prologue: stage tiles 0,1,2 (no zero-init needed; every read byte is
    // cp.async-written each stage, incl. zero-fill tails)
#pragma unroll
    for (int s = 0; s < 3; s++)
        stage_half(sgb + s * SSTAGE, sgb + s * SSTAGE + SE_BYTES,
                   Eb + (size_t)s * TROWS * 160, Vb + (size_t)s * TROWS * 16,
                   nrem0 * 10 - s * 320, nrem0 - s * TROWS, lane, p);

    float d[24];
#pragma unroll
    for (int k = 0; k < 24; k++) d[k] = 0.f;

    int buf = 0;
    for (int t = 0; t < GT; t++) {
        const int pend = GT - 1 - t;
        if (pend >= 2)      CPWAIT2();
        else if (pend == 1) CPWAIT1();
        else                CPWAIT0();
        BARSYNC64(bar);            // partner's half landed + fenced

        const uint32_t ce = sgb + (uint32_t)(buf * SSTAGE);
        const uint32_t cv = ce + SE_BYTES;

#pragma unroll
        for (int kk = 0; kk < 4; kk++) {
            const uint32_t ra = ce + (uint32_t)((kk * 8 + tig) * ROWE + g * 4);
            if (p == 0) {          // tiles (0,0)(0,1)(1,0)(1,1)(1,2)(1,3): feats m=0..3
                float f0[4], f1[4]; uint32_t u0[4], u1[4];
#pragma unroll
                for (int m = 0; m < 4; m++) {
                    LDSF(f0[m], ra + m * 32);
                    LDSF(f1[m], ra + 4 * ROWE + m * 32);
                }
#pragma unroll
                for (int m = 0; m < 4; m++) { CVT_TF32(u0[m], f0[m]); CVT_TF32(u1[m], f1[m]); }
                MMA_TF32(&d[0],  u0[0], u0[1], u1[0], u1[1], u0[0], u1[0]);
                MMA_TF32(&d[4],  u0[0], u0[1], u1[0], u1[1], u0[1], u1[1]);
                MMA_TF32(&d[8],  u0[2], u0[3], u1[2], u1[3], u0[0], u1[0]);
                MMA_TF32(&d[12], u0[2], u0[3], u1[2], u1[3], u0[1], u1[1]);
                MMA_TF32(&d[16], u0[2], u0[3], u1[2], u1[3], u0[2], u1[2]);
                MMA_TF32(&d[20], u0[2], u0[3], u1[2], u1[3], u0[3], u1[3]);
            } else {               // tiles (2,0..5): feats m=0..4 from E, m=5 from V(+zeros)
                float f0[5], f1[5]; uint32_t u0[6], u1[6];
#pragma unroll
                for (int m = 0; m < 5; m++) {
                    LDSF(f0[m], ra + m * 32);
                    LDSF(f1[m], ra + 4 * ROWE + m * 32);
                }
                float fv0 = 0.f, fv1 = 0.f;
                if (g < 4) {       // feats 40..43 live; 44..47 structurally zero
                    const uint32_t va = cv + (uint32_t)((kk * 8 + tig) * 16 + g * 4);
                    LDSF(fv0, va);
                    LDSF(fv1, va + 64);   // +4 rows * 16B
                }
#pragma unroll
                for (int m = 0; m < 5; m++) { CVT_TF32(u0[m], f0[m]); CVT_TF32(u1[m], f1[m]); }
                CVT_TF32(u0[5], fv0); CVT_TF32(u1[5], fv1);
                MMA_TF32(&d[0],  u0[4], u0[5], u1[4], u1[5], u0[0], u1[0]);
                MMA_TF32(&d[4],  u0[4], u0[5], u1[4], u1[5], u0[1], u1[1]);
                MMA_TF32(&d[8],  u0[4], u0[5], u1[4], u1[5], u0[2], u1[2]);
                MMA_TF32(&d[12], u0[4], u0[5], u1[4], u1[5], u0[3], u1[3]);
                MMA_TF32(&d[16], u0[4], u0[5], u1[4], u1[5], u0[4], u1[4]);
                MMA_TF32(&d[20], u0[4], u0[5], u1[4], u1[5], u0[5], u1[5]);
            }
        }
        BARSYNC64(bar);            // both warps done reading before overwrite

        if (t + 3 < GT)
            stage_half(ce, cv,
                       Eb + (size_t)(t + 3) * TROWS * 160,
                       Vb + (size_t)(t + 3) * TROWS * 16,
                       nrem0 * 10 - (t + 3) * 320, nrem0 - (t + 3) * TROWS, lane, p);

        buf = (buf == 2) ? 0 : buf + 1;
    }

    CPWAIT0();

    // ---- fold 4 groups: all warps dump accs, warps 0/1 sum their parity ----
    __syncthreads();
    {
        float* dst = sm + (size_t)(w * 32 + lane) * 25;   // odd stride
#pragma unroll
        for (int k = 0; k < 24; k++) dst[k] = d[k];
    }
    __syncthreads();

    float* G = sm + GOFF;   // 2304-float block, after the fold area (25.6KB)
    if (w < 2) {
        const float* fold = sm;
#pragma unroll
        for (int k = 0; k < 24; k++) {
            float s = 0.f;
#pragma unroll
            for (int e = 0; e < 4; e++)
                s += fold[(size_t)(((w + 2 * e) * 32) + lane) * 25 + k];
            d[k] = s;
        }
        // assemble FULL symmetric G in smem (computed cells + mirrors)
        const int MT0[6] = {0,0,1,1,1,1};
        const int NT0[6] = {0,1,0,1,2,3};
#pragma unroll
        for (int f = 0; f < 6; f++) {
            const int i0 = (w == 0) ? (16 * MT0[f] + g) : (32 + g);
            const int j0 = ((w == 0) ? (8 * NT0[f]) : (8 * f)) + 2 * tig;
#pragma unroll
            for (int h = 0; h < 2; h++) {
                const int ii = i0 + 8 * h;
#pragma unroll
                for (int e = 0; e < 2; e++) {
                    const float v = d[f * 4 + 2 * h + e];
                    const int jj = j0 + e;
                    G[ii * P + jj] = v;
                    G[jj * P + ii] = v;   // mirror (overlaps write same value)
                }
            }
        }
    }
    __syncthreads();

    // coalesced dump: one contiguous 9.2KB block per CTA
    {
        float4* out4 = (float4*)&g_partials[(size_t)(b * CPB + chunk) * CELLS];
        const float4* G4 = (const float4*)G;
#pragma unroll
        for (int i = tid; i < CELLS / 4; i += 256)
            out4[i] = G4[i];
    }
}

// ============================================================
// Kernel 2: per-(cell,batch) chunk reduction + weighted square.
// Consecutive threads = consecutive cells -> fully coalesced reads.
// ============================================================
__global__ __launch_bounds__(256)
void reduce1_kernel()
{
    const int idx = blockIdx.x * 256 + threadIdx.x;   // idx = b*CELLS + cell
    float v = 0.f;
    if (idx < Bb * CELLS) {
        const int b    = idx / CELLS;
        const int cell = idx - b * CELLS;
        const int i = cell / P;
        const int j = cell - i * P;
        const float* p = &g_partials[(size_t)b * CPB * CELLS + cell];
        float s0 = 0.f, s1 = 0.f, s2 = 0.f, s3 = 0.f, s4 = 0.f, s5 = 0.f;
#pragma unroll 1
        for (int c = 0; c < CPB; c += 6) {            // 54 = 9 * 6
            s0 += p[(size_t)(c + 0) * CELLS];
            s1 += p[(size_t)(c + 1) * CELLS];
            s2 += p[(size_t)(c + 2) * CELLS];
            s3 += p[(size_t)(c + 3) * CELLS];
            s4 += p[(size_t)(c + 4) * CELLS];
            s5 += p[(size_t)(c + 5) * CELLS];
        }
        const float s = ((s0 + s1) + (s2 + s3)) + (s4 + s5);
        const float wgt = ((i < Dd) == (j < Dd)) ? 1.0f : -1.0f;
        v = wgt * s * s;
    }
    __shared__ float red[256];
    red[threadIdx.x] = v;
    __syncthreads();
#pragma unroll
    for (int h = 128; h > 0; h >>= 1) {
        if (threadIdx.x < h) red[threadIdx.x] += red[threadIdx.x + h];
        __syncthreads();
    }
    if (threadIdx.x == 0) g_blocksums[blockIdx.x] = red[0];
}

// ============================================================
// Kernel 3: final scalar.
// ============================================================
__global__ __launch_bounds__(128)
void reduce2_kernel(float* __restrict__ out)
{
    __shared__ float s[128];
    const int t = threadIdx.x;
    s[t] = (t < K2_BLOCKS) ? g_blocksums[t] : 0.f;
    __syncthreads();
#pragma unroll
    for (int h = 64; h > 0; h >>= 1) {
        if (t < h) s[t] += s[t + h];
        __syncthreads();
    }
    if (t == 0) out[0] = s[0] / (float)((size_t)Bb * Nn);
}

// ============================================================
extern "C" void kernel_launch(void* const* d_in, const int* in_sizes, int n_in,
                              void* d_out, int out_size)
{
    const float* E = (const float*)d_in[0];
    const float* V = (const float*)d_in[1];
    if (n_in >= 2 && in_sizes[0] < in_sizes[1]) {
        const float* tmp = E; E = V; V = tmp;
    }

    cudaFuncSetAttribute(gram_hmma_kernel,
                         cudaFuncAttributeMaxDynamicSharedMemorySize, SMEM_BYTES);

    dim3 grid1(CPB, Bb);
    gram_hmma_kernel<<<grid1, 256, SMEM_BYTES>>>(E, V);
    reduce1_kernel<<<K2_BLOCKS, 256>>>();
    reduce2_kernel<<<1, 128>>>((float*)d_out);
}